// round 4
// baseline (speedup 1.0000x reference)
#include <cuda_runtime.h>
#include <math.h>

#define N_NODES_MAX 50000
#define D 64
#define N_REL 8

__device__ float g_agg[(size_t)N_NODES_MAX * D];   // 12.8 MB
__device__ float g_cnt[N_NODES_MAX];
__device__ float g_w[N_REL * 2 * D];               // w = W_r.sum(-1) : [8,128]
__device__ float g_y[(size_t)N_NODES_MAX * 16];    // [n][0..7]=ydst, [8..15]=ysrc

// ---------------------------------------------------------------------------
// Kernel 1: w[r][j] = sum_k W_r[r][j][k]
// ---------------------------------------------------------------------------
__global__ void wsum_kernel(const float* __restrict__ W_r) {
    int r = blockIdx.x;
    int j = threadIdx.x;
    const float4* row = (const float4*)(W_r + ((size_t)r * 2 * D + j) * D);
    float4 s = make_float4(0.f, 0.f, 0.f, 0.f);
#pragma unroll
    for (int k = 0; k < D / 4; k++) {
        float4 v = __ldg(row + k);
        s.x += v.x; s.y += v.y; s.z += v.z; s.w += v.w;
    }
    g_w[r * 2 * D + j] = (s.x + s.y) + (s.z + s.w);
}

// ---------------------------------------------------------------------------
// Kernel 1b: y tables.  y[n][j]   = dot(x[n], w[j][0:64])   j = 0..7
//                       y[n][8+j] = dot(x[n], w[j][64:128])
// Block = 256 threads = 16 nodes x 16 outputs.
// ---------------------------------------------------------------------------
__global__ __launch_bounds__(256) void y_kernel(const float* __restrict__ x, int N) {
    __shared__ float xt[D][17];   // [k][node], padded
    __shared__ float wt[D][16];   // [k][j]

    int tid = threadIdx.x;
    int base = blockIdx.x * 16;

#pragma unroll
    for (int q = 0; q < 4; q++) {
        int idx = tid + q * 256;
        int k = idx >> 4, j = idx & 15;
        wt[k][j] = (j < 8) ? g_w[j * 2 * D + k] : g_w[(j - 8) * 2 * D + D + k];
    }
    {
        int n = tid >> 4;
        int k0 = (tid & 15) * 4;
        int nn = min(base + n, N - 1);
        float4 v = __ldg((const float4*)(x + (size_t)nn * D + k0));
        xt[k0 + 0][n] = v.x; xt[k0 + 1][n] = v.y;
        xt[k0 + 2][n] = v.z; xt[k0 + 3][n] = v.w;
    }
    __syncthreads();

    int n = tid & 15, j = tid >> 4;
    float acc = 0.f;
#pragma unroll
    for (int k = 0; k < D; k++) acc += xt[k][n] * wt[k][j];

    int nn = base + n;
    if (nn < N) g_y[(size_t)nn * 16 + j] = acc;
}

// ---------------------------------------------------------------------------
// Kernel 2: zero agg + cnt
// ---------------------------------------------------------------------------
__global__ void zero_kernel(int n_nodes) {
    int idx = blockIdx.x * blockDim.x + threadIdx.x;
    int n_agg4 = n_nodes * (D / 4);
    if (idx < n_agg4) ((float4*)g_agg)[idx] = make_float4(0.f, 0.f, 0.f, 0.f);
    if (idx < n_nodes) g_cnt[idx] = 0.f;
}

// ---------------------------------------------------------------------------
// Kernel 3: edge phase. Half-warp per edge:
//   gate = sigmoid(y[dst][rel] + y[src][8+rel])
//   red.global.add.v4  agg[dst] += x[src]*gate ;  cnt[dst] += 1
// ---------------------------------------------------------------------------
__global__ void edge_kernel(const float* __restrict__ x,
                            const int* __restrict__ src,
                            const int* __restrict__ dst,
                            const int* __restrict__ rel,
                            int E) {
    int warp = (blockIdx.x * blockDim.x + threadIdx.x) >> 5;
    int lane = threadIdx.x & 31;
    int half = lane >> 4;
    int sub  = lane & 15;

    int e = warp * 2 + half;
    if (e >= E) return;

    int s = __ldg(src + e);
    int d = __ldg(dst + e);
    int r = __ldg(rel + e);

    float yd = __ldg(g_y + (size_t)d * 16 + r);
    float ys = __ldg(g_y + (size_t)s * 16 + 8 + r);
    float gate = 1.0f / (1.0f + __expf(-(yd + ys)));

    float4 xs = __ldg((const float4*)x + (size_t)s * (D / 4) + sub);

    float* addr = g_agg + (size_t)d * D + sub * 4;
    asm volatile("red.global.add.v4.f32 [%0], {%1,%2,%3,%4};"
                 :: "l"(addr), "f"(xs.x * gate), "f"(xs.y * gate),
                    "f"(xs.z * gate), "f"(xs.w * gate)
                 : "memory");
    if (sub == 0) atomicAdd(g_cnt + d, 1.0f);
}

// ---------------------------------------------------------------------------
// Kernel 4: node GEMM. K processed in two 64-wide chunks (fits 48KB smem).
//   Block: 256 threads, 64 nodes x 64 outs. Thread: 2 nodes x 8 outs.
//   csm[k][node] transposed, pad 66; wsm[o][k] broadcast reads.
//   Total static smem = 16.9 + 16 = 32.9 KB -> 3 blocks/SM.
// ---------------------------------------------------------------------------
#define BN 64
#define KCH 64

__global__ __launch_bounds__(256, 3) void node_kernel(
        const float* __restrict__ x,
        const float* __restrict__ Wl,   // [64][128]
        const float* __restrict__ b,    // [64]
        float* __restrict__ out,
        int N) {
    __shared__ float csm[KCH][66];      // 16.9 KB
    __shared__ float wsm[D][KCH];       // 16 KB

    int tid = threadIdx.x;
    int tx = tid & 31;    // node pair index
    int ty = tid >> 5;    // out group
    int base = blockIdx.x * BN;

    float acc[2][8];
#pragma unroll
    for (int j = 0; j < 8; j++) {
        float bv = __ldg(b + ty * 8 + j);
        acc[0][j] = bv; acc[1][j] = bv;
    }

#pragma unroll
    for (int kc = 0; kc < 2; kc++) {
        // ---- stage weight chunk: wsm[o][k] = Wl[o][kc*64 + k] ----
#pragma unroll
        for (int q = 0; q < 4; q++) {
            int idx = (tid + q * 256) * 4;   // float idx within 64x64 chunk
            int o = idx >> 6, k = idx & 63;
            float4 v = __ldg((const float4*)(Wl + (size_t)o * 2 * D + kc * KCH + k));
            *(float4*)&wsm[o][k] = v;
        }
        // ---- stage combined chunk, transposed: csm[k][node] ----
        {
            int n = tid & 63;
            int q16 = tid >> 6;          // 0..3 -> 16-k slice
            int k0 = q16 * 16;
            int nn = min(base + n, N - 1);
            const float4* srcp;
            float scale;
            if (kc == 0) {
                srcp = (const float4*)(x + (size_t)nn * D + k0);
                scale = 1.0f;
            } else {
                srcp = (const float4*)(g_agg + (size_t)nn * D + k0);
                scale = 1.0f / fmaxf(g_cnt[nn], 1.0f);
            }
#pragma unroll
            for (int q = 0; q < 4; q++) {
                float4 v = __ldg(srcp + q);
                int k = k0 + q * 4;
                csm[k + 0][n] = v.x * scale;
                csm[k + 1][n] = v.y * scale;
                csm[k + 2][n] = v.z * scale;
                csm[k + 3][n] = v.w * scale;
            }
        }
        __syncthreads();

        // ---- inner product over the 64-k chunk ----
#pragma unroll 8
        for (int k4 = 0; k4 < KCH; k4 += 4) {
            float4 w[8];
#pragma unroll
            for (int j = 0; j < 8; j++)
                w[j] = *(const float4*)&wsm[ty * 8 + j][k4];   // broadcast

            float2 c0 = *(const float2*)&csm[k4 + 0][tx * 2];
            float2 c1 = *(const float2*)&csm[k4 + 1][tx * 2];
            float2 c2 = *(const float2*)&csm[k4 + 2][tx * 2];
            float2 c3 = *(const float2*)&csm[k4 + 3][tx * 2];

#pragma unroll
            for (int j = 0; j < 8; j++) {
                acc[0][j] += c0.x * w[j].x; acc[1][j] += c0.y * w[j].x;
                acc[0][j] += c1.x * w[j].y; acc[1][j] += c1.y * w[j].y;
                acc[0][j] += c2.x * w[j].z; acc[1][j] += c2.y * w[j].z;
                acc[0][j] += c3.x * w[j].w; acc[1][j] += c3.y * w[j].w;
            }
        }
        __syncthreads();
    }

    // ---- epilogue: leaky relu + store ----
#pragma unroll
    for (int i = 0; i < 2; i++) {
        int n = base + tx * 2 + i;
        if (n < N) {
            float* op = out + (size_t)n * D + ty * 8;
            float4 r0, r1;
            r0.x = acc[i][0] > 0.f ? acc[i][0] : 0.01f * acc[i][0];
            r0.y = acc[i][1] > 0.f ? acc[i][1] : 0.01f * acc[i][1];
            r0.z = acc[i][2] > 0.f ? acc[i][2] : 0.01f * acc[i][2];
            r0.w = acc[i][3] > 0.f ? acc[i][3] : 0.01f * acc[i][3];
            r1.x = acc[i][4] > 0.f ? acc[i][4] : 0.01f * acc[i][4];
            r1.y = acc[i][5] > 0.f ? acc[i][5] : 0.01f * acc[i][5];
            r1.z = acc[i][6] > 0.f ? acc[i][6] : 0.01f * acc[i][6];
            r1.w = acc[i][7] > 0.f ? acc[i][7] : 0.01f * acc[i][7];
            *(float4*)op = r0;
            *(float4*)(op + 4) = r1;
        }
    }
}

// ---------------------------------------------------------------------------
extern "C" void kernel_launch(void* const* d_in, const int* in_sizes, int n_in,
                              void* d_out, int out_size) {
    const float* x    = (const float*)d_in[0];
    const int*   src  = (const int*)d_in[1];
    const int*   dst  = (const int*)d_in[2];
    const int*   rel  = (const int*)d_in[3];
    const float* W_r  = (const float*)d_in[4];
    const float* W_lin= (const float*)d_in[5];
    const float* b_lin= (const float*)d_in[6];
    float* out = (float*)d_out;

    int N = in_sizes[0] / D;     // 50000
    int E = in_sizes[1];         // 800000

    wsum_kernel<<<N_REL, 2 * D>>>(W_r);

    y_kernel<<<(N + 15) / 16, 256>>>(x, N);

    int zthreads = N * (D / 4);
    zero_kernel<<<(zthreads + 255) / 256, 256>>>(N);

    int warps = (E + 1) / 2;
    int ethreads = warps * 32;
    edge_kernel<<<(ethreads + 255) / 256, 256>>>(x, src, dst, rel, E);

    node_kernel<<<(N + BN - 1) / BN, 256>>>(x, W_lin, b_lin, out, N);
}

// round 5
// speedup vs baseline: 1.1035x; 1.1035x over previous
#include <cuda_runtime.h>
#include <math.h>

#define N_NODES_MAX 50000
#define D 64
#define N_REL 8

__device__ float g_agg[(size_t)N_NODES_MAX * D];   // 12.8 MB
__device__ float g_cnt[N_NODES_MAX];
__device__ float g_w[N_REL * 2 * D];               // w = W_r.sum(-1) : [8,128]
__device__ float g_y[(size_t)N_NODES_MAX * 16];    // [n][0..7]=ydst, [8..15]=ysrc

// ---------------------------------------------------------------------------
// Kernel 1: w[r][j] = sum_k W_r[r][j][k]
// ---------------------------------------------------------------------------
__global__ void wsum_kernel(const float* __restrict__ W_r) {
    int r = blockIdx.x;
    int j = threadIdx.x;
    const float4* row = (const float4*)(W_r + ((size_t)r * 2 * D + j) * D);
    float4 s = make_float4(0.f, 0.f, 0.f, 0.f);
#pragma unroll
    for (int k = 0; k < D / 4; k++) {
        float4 v = __ldg(row + k);
        s.x += v.x; s.y += v.y; s.z += v.z; s.w += v.w;
    }
    g_w[r * 2 * D + j] = (s.x + s.y) + (s.z + s.w);
}

// ---------------------------------------------------------------------------
// Kernel 1b: y tables.  y[n][j]   = dot(x[n], w[j][0:64])   j = 0..7
//                       y[n][8+j] = dot(x[n], w[j][64:128])
// ---------------------------------------------------------------------------
__global__ __launch_bounds__(256) void y_kernel(const float* __restrict__ x, int N) {
    __shared__ float xt[D][17];
    __shared__ float wt[D][16];

    int tid = threadIdx.x;
    int base = blockIdx.x * 16;

#pragma unroll
    for (int q = 0; q < 4; q++) {
        int idx = tid + q * 256;
        int k = idx >> 4, j = idx & 15;
        wt[k][j] = (j < 8) ? g_w[j * 2 * D + k] : g_w[(j - 8) * 2 * D + D + k];
    }
    {
        int n = tid >> 4;
        int k0 = (tid & 15) * 4;
        int nn = min(base + n, N - 1);
        float4 v = __ldg((const float4*)(x + (size_t)nn * D + k0));
        xt[k0 + 0][n] = v.x; xt[k0 + 1][n] = v.y;
        xt[k0 + 2][n] = v.z; xt[k0 + 3][n] = v.w;
    }
    __syncthreads();

    int n = tid & 15, j = tid >> 4;
    float acc = 0.f;
#pragma unroll
    for (int k = 0; k < D; k++) acc += xt[k][n] * wt[k][j];

    int nn = base + n;
    if (nn < N) g_y[(size_t)nn * 16 + j] = acc;
}

// ---------------------------------------------------------------------------
// Kernel 2: zero agg + cnt
// ---------------------------------------------------------------------------
__global__ void zero_kernel(int n_nodes) {
    int idx = blockIdx.x * blockDim.x + threadIdx.x;
    int n_agg4 = n_nodes * (D / 4);
    if (idx < n_agg4) ((float4*)g_agg)[idx] = make_float4(0.f, 0.f, 0.f, 0.f);
    if (idx < n_nodes) g_cnt[idx] = 0.f;
}

// ---------------------------------------------------------------------------
// Kernel 3: edge phase, BATCHED. Half-warp handles EB=4 edges; all loads
// front-issued (MLP ~12/thread) before any dependent compute/red.
//   gate = sigmoid(y[dst][rel] + y[src][8+rel])
//   red.global.add.v4  agg[dst] += x[src]*gate ;  cnt[dst] += 1
// ---------------------------------------------------------------------------
#define EB 4

__global__ __launch_bounds__(256) void edge_kernel(
        const float* __restrict__ x,
        const int* __restrict__ src,
        const int* __restrict__ dst,
        const int* __restrict__ rel,
        int E) {
    int gw = (blockIdx.x * blockDim.x + threadIdx.x) >> 5;
    int lane = threadIdx.x & 31;
    int half = lane >> 4;
    int sub  = lane & 15;

    int base = (gw * 2 + half) * EB;
    if (base >= E) return;

    int s[EB], d[EB], r[EB];
#pragma unroll
    for (int i = 0; i < EB; i++) {
        int e = min(base + i, E - 1);
        s[i] = __ldg(src + e);
        d[i] = __ldg(dst + e);
        r[i] = __ldg(rel + e);
    }

    float yd[EB], ys[EB];
#pragma unroll
    for (int i = 0; i < EB; i++) {
        yd[i] = __ldg(g_y + (size_t)d[i] * 16 + r[i]);
        ys[i] = __ldg(g_y + (size_t)s[i] * 16 + 8 + r[i]);
    }

    float4 xs[EB];
#pragma unroll
    for (int i = 0; i < EB; i++)
        xs[i] = __ldg((const float4*)x + (size_t)s[i] * (D / 4) + sub);

#pragma unroll
    for (int i = 0; i < EB; i++) {
        if (base + i < E) {
            float gate = 1.0f / (1.0f + __expf(-(yd[i] + ys[i])));
            float* addr = g_agg + (size_t)d[i] * D + sub * 4;
            asm volatile("red.global.add.v4.f32 [%0], {%1,%2,%3,%4};"
                         :: "l"(addr), "f"(xs[i].x * gate), "f"(xs[i].y * gate),
                            "f"(xs[i].z * gate), "f"(xs[i].w * gate)
                         : "memory");
            if (sub == 0) atomicAdd(g_cnt + d[i], 1.0f);
        }
    }
}

// ---------------------------------------------------------------------------
// Kernel 4: node GEMM. K in two 64-wide chunks; 64 nodes x 64 outs per block;
// thread: 2 nodes x 8 outs. csm[k][node] pad 66; wsm[o][k] broadcast reads.
// ---------------------------------------------------------------------------
#define BN 64
#define KCH 64

__global__ __launch_bounds__(256, 3) void node_kernel(
        const float* __restrict__ x,
        const float* __restrict__ Wl,   // [64][128]
        const float* __restrict__ b,    // [64]
        float* __restrict__ out,
        int N) {
    __shared__ float csm[KCH][66];
    __shared__ float wsm[D][KCH];

    int tid = threadIdx.x;
    int tx = tid & 31;
    int ty = tid >> 5;
    int base = blockIdx.x * BN;

    float acc[2][8];
#pragma unroll
    for (int j = 0; j < 8; j++) {
        float bv = __ldg(b + ty * 8 + j);
        acc[0][j] = bv; acc[1][j] = bv;
    }

#pragma unroll
    for (int kc = 0; kc < 2; kc++) {
#pragma unroll
        for (int q = 0; q < 4; q++) {
            int idx = (tid + q * 256) * 4;
            int o = idx >> 6, k = idx & 63;
            float4 v = __ldg((const float4*)(Wl + (size_t)o * 2 * D + kc * KCH + k));
            *(float4*)&wsm[o][k] = v;
        }
        {
            int n = tid & 63;
            int q16 = tid >> 6;
            int k0 = q16 * 16;
            int nn = min(base + n, N - 1);
            const float4* srcp;
            float scale;
            if (kc == 0) {
                srcp = (const float4*)(x + (size_t)nn * D + k0);
                scale = 1.0f;
            } else {
                srcp = (const float4*)(g_agg + (size_t)nn * D + k0);
                scale = 1.0f / fmaxf(g_cnt[nn], 1.0f);
            }
#pragma unroll
            for (int q = 0; q < 4; q++) {
                float4 v = __ldg(srcp + q);
                int k = k0 + q * 4;
                csm[k + 0][n] = v.x * scale;
                csm[k + 1][n] = v.y * scale;
                csm[k + 2][n] = v.z * scale;
                csm[k + 3][n] = v.w * scale;
            }
        }
        __syncthreads();

#pragma unroll 8
        for (int k4 = 0; k4 < KCH; k4 += 4) {
            float4 w[8];
#pragma unroll
            for (int j = 0; j < 8; j++)
                w[j] = *(const float4*)&wsm[ty * 8 + j][k4];

            float2 c0 = *(const float2*)&csm[k4 + 0][tx * 2];
            float2 c1 = *(const float2*)&csm[k4 + 1][tx * 2];
            float2 c2 = *(const float2*)&csm[k4 + 2][tx * 2];
            float2 c3 = *(const float2*)&csm[k4 + 3][tx * 2];

#pragma unroll
            for (int j = 0; j < 8; j++) {
                acc[0][j] += c0.x * w[j].x; acc[1][j] += c0.y * w[j].x;
                acc[0][j] += c1.x * w[j].y; acc[1][j] += c1.y * w[j].y;
                acc[0][j] += c2.x * w[j].z; acc[1][j] += c2.y * w[j].z;
                acc[0][j] += c3.x * w[j].w; acc[1][j] += c3.y * w[j].w;
            }
        }
        __syncthreads();
    }

#pragma unroll
    for (int i = 0; i < 2; i++) {
        int n = base + tx * 2 + i;
        if (n < N) {
            float* op = out + (size_t)n * D + ty * 8;
            float4 r0, r1;
            r0.x = acc[i][0] > 0.f ? acc[i][0] : 0.01f * acc[i][0];
            r0.y = acc[i][1] > 0.f ? acc[i][1] : 0.01f * acc[i][1];
            r0.z = acc[i][2] > 0.f ? acc[i][2] : 0.01f * acc[i][2];
            r0.w = acc[i][3] > 0.f ? acc[i][3] : 0.01f * acc[i][3];
            r1.x = acc[i][4] > 0.f ? acc[i][4] : 0.01f * acc[i][4];
            r1.y = acc[i][5] > 0.f ? acc[i][5] : 0.01f * acc[i][5];
            r1.z = acc[i][6] > 0.f ? acc[i][6] : 0.01f * acc[i][6];
            r1.w = acc[i][7] > 0.f ? acc[i][7] : 0.01f * acc[i][7];
            *(float4*)op = r0;
            *(float4*)(op + 4) = r1;
        }
    }
}

// ---------------------------------------------------------------------------
extern "C" void kernel_launch(void* const* d_in, const int* in_sizes, int n_in,
                              void* d_out, int out_size) {
    const float* x    = (const float*)d_in[0];
    const int*   src  = (const int*)d_in[1];
    const int*   dst  = (const int*)d_in[2];
    const int*   rel  = (const int*)d_in[3];
    const float* W_r  = (const float*)d_in[4];
    const float* W_lin= (const float*)d_in[5];
    const float* b_lin= (const float*)d_in[6];
    float* out = (float*)d_out;

    int N = in_sizes[0] / D;     // 50000
    int E = in_sizes[1];         // 800000

    wsum_kernel<<<N_REL, 2 * D>>>(W_r);

    y_kernel<<<(N + 15) / 16, 256>>>(x, N);

    int zthreads = N * (D / 4);
    zero_kernel<<<(zthreads + 255) / 256, 256>>>(N);

    int halves = (E + EB - 1) / EB;            // each half-warp does EB edges
    int warps = (halves + 1) / 2;
    int ethreads = warps * 32;
    edge_kernel<<<(ethreads + 255) / 256, 256>>>(x, src, dst, rel, E);

    node_kernel<<<(N + BN - 1) / BN, 256>>>(x, W_lin, b_lin, out, N);
}